// round 1
// baseline (speedup 1.0000x reference)
#include <cuda_runtime.h>
#include <cuda_bf16.h>

#define HDIM   256
#define GDIM   1024      // 4*H
#define BATCH  64
#define SEQ    512
#define NRD    10        // 5 branches * 2 directions
#define NBR    5
#define EDIM   300
#define ADIM   512       // 2*H

// ---------------- scratch (device globals; no allocation allowed) ----------------
__device__ float g_P [335544320];   // [NRD][SEQ][BATCH][GDIM]   1.34 GB gate preacts
__device__ float g_HS[ 83886080];   // [NRD][SEQ][BATCH][HDIM]   hidden states
__device__ float g_H [2][NRD][BATCH][HDIM];   // ping-pong h
__device__ float g_ATT[NBR][BATCH][ADIM];
__device__ float g_logit[NBR][BATCH][SEQ];
__device__ float g_attw [NBR][BATCH][SEQ];
__device__ unsigned g_cnt[NRD];

__device__ __forceinline__ float fsigm(float x) { return 1.0f / (1.0f + __expf(-x)); }
__device__ __forceinline__ float ftanh(float x) { return 1.0f - 2.0f / (__expf(2.0f * x) + 1.0f); }

// ---------------- init: zero counters, h ping-pong, logit accumulators -----------
__global__ void k_init() {
    int idx = blockIdx.x * blockDim.x + threadIdx.x;
    if (idx < 2 * NRD * BATCH * HDIM) ((float*)g_H)[idx] = 0.0f;
    if (idx < NBR * BATCH * SEQ)      ((float*)g_logit)[idx] = 0.0f;
    if (idx < NRD)                    g_cnt[idx] = 0u;
}

// ---------------- phase 1: input projection  P = emb[x] @ Wih.T + (bih+bhh) ------
// grid (512 m-tiles, 16 n-tiles, 10 rd), 256 threads, 64x64 tile, 4x4 microtile
__global__ void k_inputproj(const int* __restrict__ x, const float* __restrict__ emb,
                            const float* __restrict__ Wih_f, const float* __restrict__ Wih_b,
                            const float* __restrict__ bih_f, const float* __restrict__ bhh_f,
                            const float* __restrict__ bih_b, const float* __restrict__ bhh_b) {
    __shared__ __align__(16) float As[8][68];
    __shared__ __align__(16) float Bs[8][68];
    __shared__ int tok[64];
    int mtile = blockIdx.x, ntile = blockIdx.y, rd = blockIdx.z;
    int branch = rd >> 1, dir = rd & 1;
    const float* Wih = (dir ? Wih_b : Wih_f) + (size_t)branch * GDIM * EDIM;
    const float* bi  = (dir ? bih_b : bih_f) + branch * GDIM;
    const float* bh  = (dir ? bhh_b : bhh_f) + branch * GDIM;
    int tid = threadIdx.x;
    int m0 = mtile * 64, n0 = ntile * 64;
    if (tid < 64) {
        int m = m0 + tid;
        int s = m >> 6, b = m & 63;
        tok[tid] = x[b * SEQ + s];
    }
    __syncthreads();
    int ty = tid >> 4, tx = tid & 15;
    float acc[4][4];
#pragma unroll
    for (int i = 0; i < 4; i++)
#pragma unroll
        for (int j = 0; j < 4; j++) acc[i][j] = 0.0f;

    for (int k0 = 0; k0 < EDIM; k0 += 8) {
        for (int e = tid; e < 512; e += 256) {
            int mm = e >> 3, kk = e & 7;
            int k = k0 + kk;
            As[kk][mm] = (k < EDIM) ? emb[(size_t)tok[mm] * EDIM + k] : 0.0f;
        }
        for (int e = tid; e < 512; e += 256) {
            int nn = e >> 3, kk = e & 7;
            int k = k0 + kk;
            Bs[kk][nn] = (k < EDIM) ? Wih[(size_t)(n0 + nn) * EDIM + k] : 0.0f;
        }
        __syncthreads();
#pragma unroll
        for (int kk = 0; kk < 8; kk++) {
            float4 av = *(const float4*)&As[kk][ty * 4];
            float4 bv = *(const float4*)&Bs[kk][tx * 4];
            float a[4] = {av.x, av.y, av.z, av.w};
            float b[4] = {bv.x, bv.y, bv.z, bv.w};
#pragma unroll
            for (int i = 0; i < 4; i++)
#pragma unroll
                for (int j = 0; j < 4; j++) acc[i][j] = fmaf(a[i], b[j], acc[i][j]);
        }
        __syncthreads();
    }
#pragma unroll
    for (int i = 0; i < 4; i++) {
        int m = m0 + ty * 4 + i;
        int s = m >> 6, b = m & 63;
        float* Pp = g_P + (((size_t)rd * SEQ + s) * BATCH + b) * GDIM + n0;
#pragma unroll
        for (int j = 0; j < 4; j++) {
            int n = tx * 4 + j;
            Pp[n] = acc[i][j] + bi[n0 + n] + bh[n0 + n];
        }
    }
}

// ---------------- phase 2: persistent recurrent scan -----------------------------
// 80 blocks = 10 recurrences x 8 j-slices of 32. smem: Whh slice (k-major) + h (k-major).
// Thread (bt,rt): batches bt*4..+3, hidden units j0+rt and j0+rt+16, all 4 gates.
#define SCAN_SMEM ((256 * 132 + 256 * 66) * 4)

__global__ void k_scan(const float* __restrict__ Whh_f, const float* __restrict__ Whh_b) {
    extern __shared__ float sm[];
    float* swT = sm;                 // [256 k][132]  rows r = gate*32 + jl
    float* sh  = sm + 256 * 132;     // [256 k][66]   h transposed

    int rd = blockIdx.x >> 3;
    int blk = blockIdx.x & 7;
    int j0 = blk * 32;
    int branch = rd >> 1, dir = rd & 1;
    const float* W = (dir ? Whh_b : Whh_f) + (size_t)branch * GDIM * HDIM;
    int tid = threadIdx.x;

    // stage Whh slice into smem (k-major, one time)
    for (int e = tid; e < 128 * HDIM; e += 256) {
        int r = e >> 8;       // 0..127
        int k = e & 255;
        int gate = r >> 5, jl = r & 31;
        swT[k * 132 + r] = W[(size_t)(gate * HDIM + j0 + jl) * HDIM + k];
    }
    int bt = tid >> 4, rt = tid & 15;
    int b0 = bt * 4;
    float c[2][4];
#pragma unroll
    for (int a = 0; a < 2; a++)
#pragma unroll
        for (int bb = 0; bb < 4; bb++) c[a][bb] = 0.0f;
    __syncthreads();

    for (int t = 0; t < SEQ; ++t) {
        int par = t & 1;
        const float* Hin = &g_H[par][rd][0][0];
        for (int e = tid; e < BATCH * HDIM; e += 256) {
            int b = e >> 8, k = e & 255;
            sh[k * 66 + b] = Hin[e];
        }
        __syncthreads();

        int sidx = dir ? (SEQ - 1 - t) : t;
        const float* Pb = g_P + ((size_t)rd * SEQ + sidx) * BATCH * GDIM;

        float acc[8][4];
#pragma unroll
        for (int i = 0; i < 8; i++) {
            int gate = i >> 1, jl = rt + 16 * (i & 1);
#pragma unroll
            for (int bb = 0; bb < 4; bb++)
                acc[i][bb] = Pb[(size_t)(b0 + bb) * GDIM + gate * HDIM + j0 + jl];
        }
#pragma unroll 4
        for (int k = 0; k < HDIM; k++) {
            float hb[4];
#pragma unroll
            for (int bb = 0; bb < 4; bb++) hb[bb] = sh[k * 66 + b0 + bb];
#pragma unroll
            for (int i = 0; i < 8; i++) {
                float w = swT[k * 132 + rt + 16 * i];
#pragma unroll
                for (int bb = 0; bb < 4; bb++) acc[i][bb] = fmaf(w, hb[bb], acc[i][bb]);
            }
        }
        float* Hout = &g_H[par ^ 1][rd][0][0];
        float* HSo = g_HS + ((size_t)rd * SEQ + sidx) * BATCH * HDIM;
#pragma unroll
        for (int js = 0; js < 2; js++) {
            int j = j0 + rt + 16 * js;
#pragma unroll
            for (int bb = 0; bb < 4; bb++) {
                float iv = fsigm(acc[0 + js][bb]);
                float fv = fsigm(acc[2 + js][bb]);
                float gv = ftanh(acc[4 + js][bb]);
                float ov = fsigm(acc[6 + js][bb]);
                float cn = fv * c[js][bb] + iv * gv;
                c[js][bb] = cn;
                float hn = ov * ftanh(cn);
                Hout[(b0 + bb) * HDIM + j] = hn;
                HSo[(size_t)(b0 + bb) * HDIM + j] = hn;
            }
        }
        // inter-block step barrier (per recurrence)
        __threadfence();
        __syncthreads();
        if (tid == 0) {
            atomicAdd(&g_cnt[rd], 1u);
            unsigned target = 8u * (unsigned)(t + 1);
            while (atomicAdd(&g_cnt[rd], 0u) < target) __nanosleep(64);
            __threadfence();
        }
        __syncthreads();
    }
}

// ---------------- phase 3a: attention logits  l = watt . tanh(hcat @ Wa.T + ba) ---
// grid (512 m-tiles, 8 n-tiles, 5 branches), fused tanh+watt reduction, atomic acc
__global__ void k_logits(const float* __restrict__ Wa, const float* __restrict__ ba,
                         const float* __restrict__ watt) {
    __shared__ __align__(16) float As[8][68];
    __shared__ __align__(16) float Bs[8][68];
    __shared__ float red[64][17];
    int mtile = blockIdx.x, ntile = blockIdx.y, br = blockIdx.z;
    const float* W = Wa + (size_t)br * ADIM * ADIM;
    int tid = threadIdx.x;
    int m0 = mtile * 64, n0 = ntile * 64;
    int ty = tid >> 4, tx = tid & 15;
    float acc[4][4];
#pragma unroll
    for (int i = 0; i < 4; i++)
#pragma unroll
        for (int j = 0; j < 4; j++) acc[i][j] = 0.0f;

    for (int k0 = 0; k0 < ADIM; k0 += 8) {
        for (int e = tid; e < 512; e += 256) {
            int mm = e >> 3, kk = e & 7;
            int k = k0 + kk;
            int m = m0 + mm;
            int s = m >> 6, b = m & 63;
            int rdh = (k < HDIM) ? (2 * br) : (2 * br + 1);
            int dd = k & 255;
            As[kk][mm] = g_HS[(((size_t)rdh * SEQ + s) * BATCH + b) * HDIM + dd];
        }
        for (int e = tid; e < 512; e += 256) {
            int nn = e >> 3, kk = e & 7;
            Bs[kk][nn] = W[(size_t)(n0 + nn) * ADIM + k0 + kk];
        }
        __syncthreads();
#pragma unroll
        for (int kk = 0; kk < 8; kk++) {
            float4 av = *(const float4*)&As[kk][ty * 4];
            float4 bv = *(const float4*)&Bs[kk][tx * 4];
            float a[4] = {av.x, av.y, av.z, av.w};
            float b[4] = {bv.x, bv.y, bv.z, bv.w};
#pragma unroll
            for (int i = 0; i < 4; i++)
#pragma unroll
                for (int j = 0; j < 4; j++) acc[i][j] = fmaf(a[i], b[j], acc[i][j]);
        }
        __syncthreads();
    }
#pragma unroll
    for (int i = 0; i < 4; i++) {
        float part = 0.0f;
#pragma unroll
        for (int j = 0; j < 4; j++) {
            int n = n0 + tx * 4 + j;
            float u = ftanh(acc[i][j] + ba[br * ADIM + n]);
            part += u * watt[br * ADIM + n];
        }
        red[ty * 4 + i][tx] = part;
    }
    __syncthreads();
    if (tid < 64) {
        float sv = 0.0f;
#pragma unroll
        for (int q = 0; q < 16; q++) sv += red[tid][q];
        int m = m0 + tid;
        int s = m >> 6, b = m & 63;
        atomicAdd(&g_logit[br][b][s], sv);
    }
}

// ---------------- phase 3b: softmax over S -------------------------------------
__global__ void k_softmax() {
    int br = blockIdx.x >> 6, b = blockIdx.x & 63;
    __shared__ float red[256];
    const float* L = &g_logit[br][b][0];
    int tid = threadIdx.x;
    float m1 = fmaxf(L[tid], L[tid + 256]);
    red[tid] = m1; __syncthreads();
    for (int o = 128; o > 0; o >>= 1) { if (tid < o) red[tid] = fmaxf(red[tid], red[tid + o]); __syncthreads(); }
    float mx = red[0]; __syncthreads();
    float e0 = __expf(L[tid] - mx), e1 = __expf(L[tid + 256] - mx);
    red[tid] = e0 + e1; __syncthreads();
    for (int o = 128; o > 0; o >>= 1) { if (tid < o) red[tid] += red[tid + o]; __syncthreads(); }
    float inv = 1.0f / red[0];
    g_attw[br][b][tid] = e0 * inv;
    g_attw[br][b][tid + 256] = e1 * inv;
}

// ---------------- phase 3c: attention-weighted sum ------------------------------
__global__ void k_attsum() {
    int b = blockIdx.x, br = blockIdx.y;
    int d = threadIdx.x;   // 512 threads
    __shared__ float aw[512];
    aw[d] = g_attw[br][b][d];
    __syncthreads();
    int rdh = (d < HDIM) ? (2 * br) : (2 * br + 1);
    int dd = d & 255;
    const float* base = g_HS + (size_t)rdh * SEQ * BATCH * HDIM + (size_t)b * HDIM + dd;
    float a0 = 0.0f, a1 = 0.0f;
    for (int s = 0; s < SEQ; s += 2) {
        a0 = fmaf(aw[s],     base[(size_t)s * BATCH * HDIM], a0);
        a1 = fmaf(aw[s + 1], base[(size_t)(s + 1) * BATCH * HDIM], a1);
    }
    g_ATT[br][b][d] = a0 + a1;
}

// ---------------- phase 4: routed final FC --------------------------------------
__global__ void k_final(const int* __restrict__ z, const float* __restrict__ Wfc,
                        const float* __restrict__ bfc, float* __restrict__ out) {
    int b = blockIdx.x;
    int tid = threadIdx.x;   // 256
    int zb = z[b];
    __shared__ float red0[256], red1[256];
    float a0 = 0.0f, a1 = 0.0f;
    for (int k = tid; k < 1024; k += 256) {
        float v = (k < 512) ? g_ATT[zb + 1][b][k] : g_ATT[0][b][k - 512];
        a0 = fmaf(v, Wfc[k], a0);
        a1 = fmaf(v, Wfc[1024 + k], a1);
    }
    red0[tid] = a0; red1[tid] = a1; __syncthreads();
    for (int o = 128; o > 0; o >>= 1) {
        if (tid < o) { red0[tid] += red0[tid + o]; red1[tid] += red1[tid + o]; }
        __syncthreads();
    }
    if (tid == 0) {
        out[b * 2 + 0] = red0[0] + bfc[0];
        out[b * 2 + 1] = red1[0] + bfc[1];
    }
}

// ---------------- copy general + specifics into d_out ---------------------------
__global__ void k_copyout(float* __restrict__ out) {
    int idx = blockIdx.x * blockDim.x + threadIdx.x;
    const float* A = &g_ATT[0][0][0];
    if (idx < NBR * BATCH * ADIM) out[128 + idx] = A[idx];
}

// ---------------- launcher -------------------------------------------------------
extern "C" void kernel_launch(void* const* d_in, const int* in_sizes, int n_in,
                              void* d_out, int out_size) {
    const int*   x     = (const int*)  d_in[0];
    const int*   z     = (const int*)  d_in[1];
    const float* emb   = (const float*)d_in[2];
    const float* Wih_f = (const float*)d_in[3];
    const float* Whh_f = (const float*)d_in[4];
    const float* bih_f = (const float*)d_in[5];
    const float* bhh_f = (const float*)d_in[6];
    const float* Wih_b = (const float*)d_in[7];
    const float* Whh_b = (const float*)d_in[8];
    const float* bih_b = (const float*)d_in[9];
    const float* bhh_b = (const float*)d_in[10];
    const float* Wa    = (const float*)d_in[11];
    const float* ba    = (const float*)d_in[12];
    const float* watt  = (const float*)d_in[13];
    const float* Wfc   = (const float*)d_in[14];
    const float* bfc   = (const float*)d_in[15];
    float* out = (float*)d_out;

    cudaFuncSetAttribute(k_scan, cudaFuncAttributeMaxDynamicSharedMemorySize, SCAN_SMEM);

    k_init<<<1280, 256>>>();
    k_inputproj<<<dim3(512, 16, 10), 256>>>(x, emb, Wih_f, Wih_b, bih_f, bhh_f, bih_b, bhh_b);
    k_scan<<<80, 256, SCAN_SMEM>>>(Whh_f, Whh_b);
    k_logits<<<dim3(512, 8, 5), 256>>>(Wa, ba, watt);
    k_softmax<<<320, 256>>>();
    k_attsum<<<dim3(64, 5), 512>>>();
    k_final<<<64, 256>>>(z, Wfc, bfc, out);
    k_copyout<<<640, 256>>>(out);
}

// round 2
// speedup vs baseline: 1.0732x; 1.0732x over previous
#include <cuda_runtime.h>
#include <cuda_bf16.h>

#define HDIM   256
#define GDIM   1024      // 4*H
#define BATCH  64
#define SEQ    512
#define NRD    10        // 5 branches * 2 directions
#define NBR    5
#define EDIM   300
#define ADIM   512       // 2*H

typedef unsigned long long ull;

// ---------------- scratch (device globals; no allocation allowed) ----------------
__device__ float g_P [335544320];   // [NRD][SEQ][BATCH][GDIM]
__device__ float g_HS[ 83886080];   // [NRD][SEQ][BATCH][HDIM]
__device__ float g_H [2][NRD][BATCH][HDIM];
__device__ float g_ATT[NBR][BATCH][ADIM];
__device__ float g_logit[NBR][BATCH][SEQ];
__device__ float g_attw [NBR][BATCH][SEQ];
__device__ unsigned g_cnt[NRD];

__device__ __forceinline__ float fsigm(float x) { return 1.0f / (1.0f + __expf(-x)); }
__device__ __forceinline__ float ftanh(float x) { return 1.0f - 2.0f / (__expf(2.0f * x) + 1.0f); }

__device__ __forceinline__ ull pk2(float lo, float hi) {
    ull r; asm("mov.b64 %0, {%1, %2};" : "=l"(r) : "f"(lo), "f"(hi)); return r;
}
__device__ __forceinline__ ull dup2(float v) { return pk2(v, v); }
__device__ __forceinline__ void fma2(ull& d, ull a, ull b) {
    asm("fma.rn.f32x2 %0, %1, %2, %3;" : "=l"(d) : "l"(a), "l"(b), "l"(d));
}
__device__ __forceinline__ void unpk2(ull v, float& lo, float& hi) {
    asm("mov.b64 {%0, %1}, %2;" : "=f"(lo), "=f"(hi) : "l"(v));
}

// ---------------- init -----------------------------------------------------------
__global__ void k_init() {
    int idx = blockIdx.x * blockDim.x + threadIdx.x;
    if (idx < 2 * NRD * BATCH * HDIM) ((float*)g_H)[idx] = 0.0f;
    if (idx < NBR * BATCH * SEQ)      ((float*)g_logit)[idx] = 0.0f;
    if (idx < NRD)                    g_cnt[idx] = 0u;
}

// ---------------- phase 1: P = emb[x] @ Wih.T + (bih+bhh) ------------------------
// 128x64 tile, 256 threads, 8x4 microtile, f32x2 accumulators paired over m
__global__ void k_inputproj(const int* __restrict__ x, const float* __restrict__ emb,
                            const float* __restrict__ Wih_f, const float* __restrict__ Wih_b,
                            const float* __restrict__ bih_f, const float* __restrict__ bhh_f,
                            const float* __restrict__ bih_b, const float* __restrict__ bhh_b) {
    __shared__ __align__(16) float As[8][132];
    __shared__ __align__(16) float Bs[8][68];
    __shared__ int tok[128];
    int mtile = blockIdx.x, ntile = blockIdx.y, rd = blockIdx.z;
    int branch = rd >> 1, dir = rd & 1;
    const float* Wih = (dir ? Wih_b : Wih_f) + (size_t)branch * GDIM * EDIM;
    const float* bi  = (dir ? bih_b : bih_f) + branch * GDIM;
    const float* bh  = (dir ? bhh_b : bhh_f) + branch * GDIM;
    int tid = threadIdx.x;
    int m0 = mtile * 128, n0 = ntile * 64;
    if (tid < 128) {
        int m = m0 + tid;
        int s = m >> 6, b = m & 63;
        tok[tid] = x[b * SEQ + s];
    }
    __syncthreads();
    int ty = tid >> 4, tx = tid & 15;   // ty: 8 m-rows, tx: 4 n-cols
    ull acc[4][4];                       // [m-pair][n]
#pragma unroll
    for (int p = 0; p < 4; p++)
#pragma unroll
        for (int j = 0; j < 4; j++) acc[p][j] = 0ull;

    for (int k0 = 0; k0 < 304; k0 += 8) {
        for (int e = tid; e < 1024; e += 256) {
            int mm = e >> 3, kk = e & 7;
            int k = k0 + kk;
            As[kk][mm] = (k < EDIM) ? emb[(size_t)tok[mm] * EDIM + k] : 0.0f;
        }
        for (int e = tid; e < 512; e += 256) {
            int nn = e >> 3, kk = e & 7;
            int k = k0 + kk;
            Bs[kk][nn] = (k < EDIM) ? Wih[(size_t)(n0 + nn) * EDIM + k] : 0.0f;
        }
        __syncthreads();
#pragma unroll
        for (int kk = 0; kk < 8; kk++) {
            ull ap[4];
#pragma unroll
            for (int p = 0; p < 4; p++) ap[p] = *(const ull*)&As[kk][ty * 8 + 2 * p];
            float4 bv = *(const float4*)&Bs[kk][tx * 4];
            ull bd[4] = {dup2(bv.x), dup2(bv.y), dup2(bv.z), dup2(bv.w)};
#pragma unroll
            for (int p = 0; p < 4; p++)
#pragma unroll
                for (int j = 0; j < 4; j++) fma2(acc[p][j], ap[p], bd[j]);
        }
        __syncthreads();
    }
#pragma unroll
    for (int p = 0; p < 4; p++) {
#pragma unroll
        for (int q = 0; q < 2; q++) {
            int m = m0 + ty * 8 + 2 * p + q;
            int s = m >> 6, b = m & 63;
            float* Pp = g_P + (((size_t)rd * SEQ + s) * BATCH + b) * GDIM + n0;
#pragma unroll
            for (int j = 0; j < 4; j++) {
                int n = tx * 4 + j;
                float lo, hi; unpk2(acc[p][j], lo, hi);
                float v = q ? hi : lo;
                Pp[n] = v + bi[n0 + n] + bh[n0 + n];
            }
        }
    }
}

// ---------------- phase 2: persistent recurrent scan (f32x2) ---------------------
// 80 blocks = 10 rec x 8 j-slices of 32. swT stores (j, j+16) w pairs adjacent.
#define SCAN_SMEM ((256 * 132 + 256 * 68) * 4)

__global__ void k_scan(const float* __restrict__ Whh_f, const float* __restrict__ Whh_b) {
    extern __shared__ float sm[];
    float* swT = sm;                 // [256 k][132]: slot gate*32 + 2*jl + half
    float* sh  = sm + 256 * 132;     // [256 k][68]:  h transposed

    int rd = blockIdx.x >> 3;
    int blk = blockIdx.x & 7;
    int j0 = blk * 32;
    int branch = rd >> 1, dir = rd & 1;
    const float* W = (dir ? Whh_b : Whh_f) + (size_t)branch * GDIM * HDIM;
    int tid = threadIdx.x;

    // stage Whh slice: pair layout (jl, jl+16) adjacent for ld.shared.b64
    for (int e = tid; e < 128 * HDIM; e += 256) {
        int r = e >> 8;       // 0..127
        int k = e & 255;
        int gate = r >> 5, jl = r & 31;
        int slot = gate * 32 + 2 * (jl & 15) + (jl >> 4);
        swT[k * 132 + slot] = W[(size_t)(gate * HDIM + j0 + jl) * HDIM + k];
    }
    int bt = tid >> 4, rt = tid & 15;
    int b0 = bt * 4;
    float c[2][4];
#pragma unroll
    for (int a = 0; a < 2; a++)
#pragma unroll
        for (int bb = 0; bb < 4; bb++) c[a][bb] = 0.0f;
    __syncthreads();

    for (int t = 0; t < SEQ; ++t) {
        int par = t & 1;
        const float* Hin = &g_H[par][rd][0][0];
        for (int e = tid; e < BATCH * HDIM; e += 256) {
            int b = e >> 8, k = e & 255;
            sh[k * 68 + b] = Hin[e];
        }
        __syncthreads();

        int sidx = dir ? (SEQ - 1 - t) : t;
        const float* Pb = g_P + ((size_t)rd * SEQ + sidx) * BATCH * GDIM;

        ull acc[4][4];   // [gate][batch], pair = (j0+rt, j0+rt+16)
#pragma unroll
        for (int g = 0; g < 4; g++)
#pragma unroll
            for (int bb = 0; bb < 4; bb++) {
                const float* pp = Pb + (size_t)(b0 + bb) * GDIM + g * HDIM + j0 + rt;
                acc[g][bb] = pk2(pp[0], pp[16]);
            }
#pragma unroll 4
        for (int k = 0; k < HDIM; k++) {
            float4 hb4 = *(const float4*)&sh[k * 68 + b0];
            ull hd[4] = {dup2(hb4.x), dup2(hb4.y), dup2(hb4.z), dup2(hb4.w)};
#pragma unroll
            for (int g = 0; g < 4; g++) {
                ull wp = *(const ull*)&swT[k * 132 + g * 32 + 2 * rt];
#pragma unroll
                for (int bb = 0; bb < 4; bb++) fma2(acc[g][bb], wp, hd[bb]);
            }
        }
        float* Hout = &g_H[par ^ 1][rd][0][0];
        float* HSo = g_HS + ((size_t)rd * SEQ + sidx) * BATCH * HDIM;
#pragma unroll
        for (int bb = 0; bb < 4; bb++) {
            float i0, i1, f0, f1, gg0, gg1, o0, o1;
            unpk2(acc[0][bb], i0, i1);
            unpk2(acc[1][bb], f0, f1);
            unpk2(acc[2][bb], gg0, gg1);
            unpk2(acc[3][bb], o0, o1);
            float cn0 = fsigm(f0) * c[0][bb] + fsigm(i0) * ftanh(gg0);
            float cn1 = fsigm(f1) * c[1][bb] + fsigm(i1) * ftanh(gg1);
            c[0][bb] = cn0; c[1][bb] = cn1;
            float h0 = fsigm(o0) * ftanh(cn0);
            float h1 = fsigm(o1) * ftanh(cn1);
            int j = j0 + rt;
            Hout[(b0 + bb) * HDIM + j]      = h0;
            Hout[(b0 + bb) * HDIM + j + 16] = h1;
            HSo[(size_t)(b0 + bb) * HDIM + j]      = h0;
            HSo[(size_t)(b0 + bb) * HDIM + j + 16] = h1;
        }
        __threadfence();
        __syncthreads();
        if (tid == 0) {
            atomicAdd(&g_cnt[rd], 1u);
            unsigned target = 8u * (unsigned)(t + 1);
            while (atomicAdd(&g_cnt[rd], 0u) < target) __nanosleep(64);
            __threadfence();
        }
        __syncthreads();
    }
}

// ---------------- phase 3a: attention logits (f32x2 GEMM, fused tanh+watt) -------
__global__ void k_logits(const float* __restrict__ Wa, const float* __restrict__ ba,
                         const float* __restrict__ watt) {
    __shared__ __align__(16) float As[8][132];
    __shared__ __align__(16) float Bs[8][68];
    __shared__ float red[128][17];
    int mtile = blockIdx.x, ntile = blockIdx.y, br = blockIdx.z;
    const float* W = Wa + (size_t)br * ADIM * ADIM;
    int tid = threadIdx.x;
    int m0 = mtile * 128, n0 = ntile * 64;
    int ty = tid >> 4, tx = tid & 15;
    ull acc[4][4];
#pragma unroll
    for (int p = 0; p < 4; p++)
#pragma unroll
        for (int j = 0; j < 4; j++) acc[p][j] = 0ull;

    for (int k0 = 0; k0 < ADIM; k0 += 8) {
        for (int e = tid; e < 1024; e += 256) {
            int mm = e >> 3, kk = e & 7;
            int k = k0 + kk;
            int m = m0 + mm;
            int s = m >> 6, b = m & 63;
            int rdh = 2 * br + (k >> 8);
            int dd = k & 255;
            As[kk][mm] = g_HS[(((size_t)rdh * SEQ + s) * BATCH + b) * HDIM + dd];
        }
        for (int e = tid; e < 512; e += 256) {
            int nn = e >> 3, kk = e & 7;
            Bs[kk][nn] = W[(size_t)(n0 + nn) * ADIM + k0 + kk];
        }
        __syncthreads();
#pragma unroll
        for (int kk = 0; kk < 8; kk++) {
            ull ap[4];
#pragma unroll
            for (int p = 0; p < 4; p++) ap[p] = *(const ull*)&As[kk][ty * 8 + 2 * p];
            float4 bv = *(const float4*)&Bs[kk][tx * 4];
            ull bd[4] = {dup2(bv.x), dup2(bv.y), dup2(bv.z), dup2(bv.w)};
#pragma unroll
            for (int p = 0; p < 4; p++)
#pragma unroll
                for (int j = 0; j < 4; j++) fma2(acc[p][j], ap[p], bd[j]);
        }
        __syncthreads();
    }
#pragma unroll
    for (int p = 0; p < 4; p++) {
#pragma unroll
        for (int q = 0; q < 2; q++) {
            float part = 0.0f;
#pragma unroll
            for (int j = 0; j < 4; j++) {
                int n = n0 + tx * 4 + j;
                float lo, hi; unpk2(acc[p][j], lo, hi);
                float v = q ? hi : lo;
                float u = ftanh(v + ba[br * ADIM + n]);
                part += u * watt[br * ADIM + n];
            }
            red[ty * 8 + 2 * p + q][tx] = part;
        }
    }
    __syncthreads();
    if (tid < 128) {
        float sv = 0.0f;
#pragma unroll
        for (int qq = 0; qq < 16; qq++) sv += red[tid][qq];
        int m = m0 + tid;
        int s = m >> 6, b = m & 63;
        atomicAdd(&g_logit[br][b][s], sv);
    }
}

// ---------------- phase 3b: softmax over S -------------------------------------
__global__ void k_softmax() {
    int br = blockIdx.x >> 6, b = blockIdx.x & 63;
    __shared__ float red[256];
    const float* L = &g_logit[br][b][0];
    int tid = threadIdx.x;
    float m1 = fmaxf(L[tid], L[tid + 256]);
    red[tid] = m1; __syncthreads();
    for (int o = 128; o > 0; o >>= 1) { if (tid < o) red[tid] = fmaxf(red[tid], red[tid + o]); __syncthreads(); }
    float mx = red[0]; __syncthreads();
    float e0 = __expf(L[tid] - mx), e1 = __expf(L[tid + 256] - mx);
    red[tid] = e0 + e1; __syncthreads();
    for (int o = 128; o > 0; o >>= 1) { if (tid < o) red[tid] += red[tid + o]; __syncthreads(); }
    float inv = 1.0f / red[0];
    g_attw[br][b][tid] = e0 * inv;
    g_attw[br][b][tid + 256] = e1 * inv;
}

// ---------------- phase 3c: attention-weighted sum ------------------------------
__global__ void k_attsum() {
    int b = blockIdx.x, br = blockIdx.y;
    int d = threadIdx.x;   // 512 threads
    __shared__ float aw[512];
    aw[d] = g_attw[br][b][d];
    __syncthreads();
    int rdh = (d < HDIM) ? (2 * br) : (2 * br + 1);
    int dd = d & 255;
    const float* base = g_HS + (size_t)rdh * SEQ * BATCH * HDIM + (size_t)b * HDIM + dd;
    float a0 = 0.0f, a1 = 0.0f;
    for (int s = 0; s < SEQ; s += 2) {
        a0 = fmaf(aw[s],     base[(size_t)s * BATCH * HDIM], a0);
        a1 = fmaf(aw[s + 1], base[(size_t)(s + 1) * BATCH * HDIM], a1);
    }
    g_ATT[br][b][d] = a0 + a1;
}

// ---------------- phase 4: routed final FC --------------------------------------
__global__ void k_final(const int* __restrict__ z, const float* __restrict__ Wfc,
                        const float* __restrict__ bfc, float* __restrict__ out) {
    int b = blockIdx.x;
    int tid = threadIdx.x;   // 256
    int zb = z[b];
    __shared__ float red0[256], red1[256];
    float a0 = 0.0f, a1 = 0.0f;
    for (int k = tid; k < 1024; k += 256) {
        float v = (k < 512) ? g_ATT[zb + 1][b][k] : g_ATT[0][b][k - 512];
        a0 = fmaf(v, Wfc[k], a0);
        a1 = fmaf(v, Wfc[1024 + k], a1);
    }
    red0[tid] = a0; red1[tid] = a1; __syncthreads();
    for (int o = 128; o > 0; o >>= 1) {
        if (tid < o) { red0[tid] += red0[tid + o]; red1[tid] += red1[tid + o]; }
        __syncthreads();
    }
    if (tid == 0) {
        out[b * 2 + 0] = red0[0] + bfc[0];
        out[b * 2 + 1] = red1[0] + bfc[1];
    }
}

// ---------------- copy general + specifics into d_out ---------------------------
__global__ void k_copyout(float* __restrict__ out) {
    int idx = blockIdx.x * blockDim.x + threadIdx.x;
    const float* A = &g_ATT[0][0][0];
    if (idx < NBR * BATCH * ADIM) out[128 + idx] = A[idx];
}

// ---------------- launcher -------------------------------------------------------
extern "C" void kernel_launch(void* const* d_in, const int* in_sizes, int n_in,
                              void* d_out, int out_size) {
    const int*   x     = (const int*)  d_in[0];
    const int*   z     = (const int*)  d_in[1];
    const float* emb   = (const float*)d_in[2];
    const float* Wih_f = (const float*)d_in[3];
    const float* Whh_f = (const float*)d_in[4];
    const float* bih_f = (const float*)d_in[5];
    const float* bhh_f = (const float*)d_in[6];
    const float* Wih_b = (const float*)d_in[7];
    const float* Whh_b = (const float*)d_in[8];
    const float* bih_b = (const float*)d_in[9];
    const float* bhh_b = (const float*)d_in[10];
    const float* Wa    = (const float*)d_in[11];
    const float* ba    = (const float*)d_in[12];
    const float* watt  = (const float*)d_in[13];
    const float* Wfc   = (const float*)d_in[14];
    const float* bfc   = (const float*)d_in[15];
    float* out = (float*)d_out;

    cudaFuncSetAttribute(k_scan, cudaFuncAttributeMaxDynamicSharedMemorySize, SCAN_SMEM);

    k_init<<<1280, 256>>>();
    k_inputproj<<<dim3(256, 16, 10), 256>>>(x, emb, Wih_f, Wih_b, bih_f, bhh_f, bih_b, bhh_b);
    k_scan<<<80, 256, SCAN_SMEM>>>(Whh_f, Whh_b);
    k_logits<<<dim3(256, 8, 5), 256>>>(Wa, ba, watt);
    k_softmax<<<320, 256>>>();
    k_attsum<<<dim3(64, 5), 512>>>();
    k_final<<<64, 256>>>(z, Wfc, bfc, out);
    k_copyout<<<640, 256>>>(out);
}